// round 14
// baseline (speedup 1.0000x reference)
#include <cuda_runtime.h>

// SPD log-map: for each 64x64 SPD matrix A, compute logm(A) = U diag(log w) U^T
// and emit the row-major upper triangle (2080 floats).
//
// One-sided Jacobi on B := A; at convergence columns are orthogonal with
// norms = eigenvalues, and logm(A) = B diag(log(l)/l^2) B^T.
//
// R13: recursive-halving Jacobi ordering. Sweep = 6 phases (b = 32,16,8,4,2,1
// rounds). Within a phase each 16-lane group pins its p-column in REGISTERS;
// only q-columns move through smem (1 LDS.128 + <=1 STS.128 per round, vs
// 2+2 for the round-robin tournament) -> ~45% less smem traffic on an
// L1-crossbar-bound kernel. Every unordered pair is visited exactly once per
// sweep (a pair splits at exactly one recursion level).
// Keeps R12: f32x2 packed math, MUFU div/sqrt, LDS.128 layout, adaptive stop.

#define MDIM 64
#define LDF  68          // floats per column slot (column base 272B, 16B-aligned)
#define LD4  17          // float4 stride
#define MAXSWEEP 24
#define NTRI 2080
#define RTOL 1e-13f      // rotate above ~3e-7 relative orthogonality
#define QTOL 1e-8f       // sweep "significant" above ~1e-4 relative

typedef unsigned long long u64;

__device__ __forceinline__ u64 pk2(float x, float y) {
    u64 r; asm("mov.b64 %0, {%1, %2};" : "=l"(r) : "f"(x), "f"(y)); return r;
}
__device__ __forceinline__ float2 upk(u64 v) {
    float lo, hi; asm("mov.b64 {%0, %1}, %2;" : "=f"(lo), "=f"(hi) : "l"(v));
    return make_float2(lo, hi);
}
__device__ __forceinline__ u64 mul2(u64 a, u64 b) {
    u64 r; asm("mul.rn.f32x2 %0, %1, %2;" : "=l"(r) : "l"(a), "l"(b)); return r;
}
__device__ __forceinline__ u64 fma2(u64 a, u64 b, u64 c) {
    u64 r; asm("fma.rn.f32x2 %0, %1, %2, %3;" : "=l"(r) : "l"(a), "l"(b), "l"(c));
    return r;
}

__device__ __forceinline__ float half_sum(float v) {
    #pragma unroll
    for (int o = 8; o; o >>= 1)
        v += __shfl_xor_sync(0xffffffffu, v, o);
    return v;                 // sum within each 16-lane half-warp
}

__global__ __launch_bounds__(512, 4)
void spd_log_kernel(const float* __restrict__ in, float* __restrict__ out)
{
    __shared__ float4 Bs4[MDIM * LD4];  // column c: float4 g = rows 4g..4g+3
    __shared__ float  cn[MDIM];
    __shared__ float  dv[MDIM];
    __shared__ int    nsig;

    const int tid    = threadIdx.x;
    const int pairid = tid >> 4;        // 0..31: half-warp (group) id
    const int hl     = tid & 15;        // lane within group
    const int warp   = tid >> 5;        // 0..15
    const int lane   = tid & 31;

    float* Bf = (float*)Bs4;            // B[r, c] == Bf[c*LDF + r]

    const float* A = in  + (size_t)blockIdx.x * (MDIM * MDIM);
    float*       O = out + (size_t)blockIdx.x * NTRI;

    // Load (A symmetric): Bf[c*LDF + r] = A[c*64 + r]; contiguous both sides.
    for (int e = tid; e < MDIM * MDIM; e += 512) {
        int c = e >> 6, r = e & 63;
        Bf[c * LDF + r] = A[e];
    }
    if (tid == 0) nsig = 0;
    __syncthreads();

    // ---- One-sided Jacobi sweeps (adaptive) ----
    for (int sw = 0; sw < MAXSWEEP; sw++) {
        // Exact column norms at sweep start: group g -> cols g, g+32.
        #pragma unroll
        for (int h = 0; h < 2; h++) {
            int k = pairid + 32 * h;
            float4 X = Bs4[k * LD4 + hl];
            u64 xa = pk2(X.x, X.y), xb = pk2(X.z, X.w);
            float2 f = upk(fma2(xb, xb, mul2(xa, xa)));
            float n2 = half_sum(f.x + f.y);
            if (hl == 0) cn[k] = n2;
        }
        __syncthreads();

        // 6 phases: b = 32, 16, 8, 4, 2, 1 rounds.
        for (int lev = 0; lev < 6; lev++) {
            const int b    = 32 >> lev;             // columns per side
            const int i    = pairid & (b - 1);      // local index in subproblem
            const int base = (pairid & ~(b - 1)) << 1;  // subproblem start col
            const int pcol = base + i;

            // Pin p-column in registers for the whole phase.
            float4 P  = Bs4[pcol * LD4 + hl];
            float app = cn[pcol];
            u64 pxy = pk2(P.x, P.y), pzw = pk2(P.z, P.w);

            int qoff = i;
            for (int r = 0; r < b; r++) {
                const int qcol = base + b + qoff;
                float4 Q  = Bs4[qcol * LD4 + hl];
                float aqq = cn[qcol];

                u64 qxy = pk2(Q.x, Q.y), qzw = pk2(Q.z, Q.w);
                float2 df = upk(fma2(pzw, qzw, mul2(pxy, qxy)));
                float apq = half_sum(df.x + df.y);

                float a2 = apq * apq, pr = app * aqq;
                bool rot = a2 > RTOL * pr;          // uniform per group
                if (__any_sync(0xffffffffu, rot)) {
                    float th  = __fdividef(aqq - app, 2.0f * apq);
                    float h2  = fmaf(th, th, 1.0f);
                    float hyp = h2 * rsqrtf(h2);             // sqrt(1+th^2)
                    float t   = copysignf(__fdividef(1.0f, fabsf(th) + hyp), th);
                    float c   = rsqrtf(fmaf(t, t, 1.0f));
                    float s   = t * c;

                    if (rot) {
                        u64 cc = pk2(c, c), ss = pk2(s, s), ns = pk2(-s, -s);
                        u64 nPxy = fma2(cc, pxy, mul2(ns, qxy));
                        u64 nPzw = fma2(cc, pzw, mul2(ns, qzw));
                        float2 b0 = upk(fma2(cc, qxy, mul2(ss, pxy)));
                        float2 b1 = upk(fma2(cc, qzw, mul2(ss, pzw)));
                        pxy = nPxy; pzw = nPzw;
                        Bs4[qcol * LD4 + hl] = make_float4(b0.x, b0.y, b1.x, b1.y);
                        app = app - t * apq;
                        if (hl == 0) {
                            cn[qcol] = aqq + t * apq;
                            if (a2 > QTOL * pr) nsig = 1;
                        }
                    }
                }
                __syncthreads();
                qoff++; if (qoff == b) qoff = 0;
            }

            // Phase end: spill p-column back to its slot.
            {
                float2 f0 = upk(pxy), f1 = upk(pzw);
                Bs4[pcol * LD4 + hl] = make_float4(f0.x, f0.y, f1.x, f1.y);
                if (hl == 0) cn[pcol] = app;
            }
            __syncthreads();
        }

        int sdone = nsig;
        __syncthreads();
        if (tid == 0) nsig = 0;
        __syncthreads();
        if (sdone == 0) break;
    }

    // ---- dv_k = log(l_k)/l_k^2 = 0.5*log(n2)/n2, n2 = l^2 ----
    #pragma unroll
    for (int h = 0; h < 2; h++) {
        int k = pairid + 32 * h;
        float4 X = Bs4[k * LD4 + hl];
        u64 xa = pk2(X.x, X.y), xb = pk2(X.z, X.w);
        float2 f = upk(fma2(xb, xb, mul2(xa, xa)));
        float n2 = half_sum(f.x + f.y);
        if (hl == 0) dv[k] = 0.5f * logf(n2) / n2;
    }
    __syncthreads();

    // ---- out[i][j] = sum_k dv[k]*B[i,k]*B[j,k], i<=j.
    //      Warp w owns rows {w, 63-w, 16+w, 47-w}; lanes cover j-pairs with
    //      float2 loads + packed FMA. ----
    #pragma unroll
    for (int rsel = 0; rsel < 4; rsel++) {
        int i = (rsel == 0) ? warp
              : (rsel == 1) ? 63 - warp
              : (rsel == 2) ? 16 + warp
                            : 47 - warp;
        int basei = i * (129 - i) / 2;
        int je = i & ~1;                 // even start so float2 loads align
        int j0 = je + 2 * lane;
        if (j0 < MDIM) {
            u64 acc = 0;                 // packed (0.0f, 0.0f)
            #pragma unroll
            for (int k = 0; k < MDIM; k++) {
                float ci = dv[k] * Bf[k * LDF + i];
                const float2 bj = *(const float2*)(Bf + k * LDF + j0);
                acc = fma2(pk2(ci, ci), pk2(bj.x, bj.y), acc);
            }
            float2 r = upk(acc);
            if (j0 >= i) O[basei + (j0 - i)] = r.x;
            O[basei + (j0 + 1 - i)] = r.y;
        }
    }
}

extern "C" void kernel_launch(void* const* d_in, const int* in_sizes, int n_in,
                              void* d_out, int out_size)
{
    const float* A = (const float*)d_in[0];
    float* out = (float*)d_out;
    int batch = in_sizes[0] / (MDIM * MDIM);   // 8192
    spd_log_kernel<<<batch, 512>>>(A, out);
}

// round 15
// speedup vs baseline: 1.2402x; 1.2402x over previous
#include <cuda_runtime.h>

// SPD log-map: for each 64x64 SPD matrix A, compute logm(A) = U diag(log w) U^T
// and emit the row-major upper triangle (2080 floats).
//
// R15 = R12 sweep machinery, but on the CHOLESKY FACTOR:
//   A = L L^T (in-place smem Cholesky, ~1 sweep cost), then one-sided Jacobi
//   on B := L. Gram = L^T L ~ A has cond 4e3 instead of cond(A^2)=1.6e7 ->
//   fewer sweeps. At convergence ||w_k||^2 = lambda_k and
//   logm(A) = W diag(log(l_k)/l_k) W^T  (dv = log(n2)/n2).
// Sweep loop identical to R12: 512 thr, 16-lane group per column pair,
// LDS.128 column slices (LDF=68), f32x2 packed math, MUFU div/sqrt,
// adaptive sweep stop, 1 barrier/round.

#define MDIM 64
#define LDF  68          // floats per column slot (column base 272B, 16B-aligned)
#define LD4  17          // float4 stride
#define MAXSWEEP 24
#define NTRI 2080
#define RTOL 1e-13f      // rotate above ~3e-7 relative orthogonality
#define QTOL 1e-8f       // sweep "significant" above ~1e-4 relative

typedef unsigned long long u64;

__device__ __forceinline__ u64 pk2(float x, float y) {
    u64 r; asm("mov.b64 %0, {%1, %2};" : "=l"(r) : "f"(x), "f"(y)); return r;
}
__device__ __forceinline__ float2 upk(u64 v) {
    float lo, hi; asm("mov.b64 {%0, %1}, %2;" : "=f"(lo), "=f"(hi) : "l"(v));
    return make_float2(lo, hi);
}
__device__ __forceinline__ u64 mul2(u64 a, u64 b) {
    u64 r; asm("mul.rn.f32x2 %0, %1, %2;" : "=l"(r) : "l"(a), "l"(b)); return r;
}
__device__ __forceinline__ u64 fma2(u64 a, u64 b, u64 c) {
    u64 r; asm("fma.rn.f32x2 %0, %1, %2, %3;" : "=l"(r) : "l"(a), "l"(b), "l"(c));
    return r;
}

__device__ __forceinline__ float half_sum(float v) {
    #pragma unroll
    for (int o = 8; o; o >>= 1)
        v += __shfl_xor_sync(0xffffffffu, v, o);
    return v;                 // sum within each 16-lane half-warp
}

__global__ __launch_bounds__(512, 4)
void spd_log_kernel(const float* __restrict__ in, float* __restrict__ out)
{
    __shared__ float4 Bs4[MDIM * LD4];  // column c: float4 g = rows 4g..4g+3
    __shared__ float  cn[MDIM];
    __shared__ float  dv[MDIM];
    __shared__ int    nsig;

    const int tid    = threadIdx.x;
    const int pairid = tid >> 4;        // 0..31: half-warp (group) id
    const int hl     = tid & 15;        // lane within group
    const int warp   = tid >> 5;        // 0..15
    const int lane   = tid & 31;

    float* Bf = (float*)Bs4;            // B[r, c] == Bf[c*LDF + r]

    const float* A = in  + (size_t)blockIdx.x * (MDIM * MDIM);
    float*       O = out + (size_t)blockIdx.x * NTRI;

    // Load (A symmetric): Bf[c*LDF + r] = A[c*64 + r]; contiguous both sides.
    for (int e = tid; e < MDIM * MDIM; e += 512) {
        int c = e >> 6, r = e & 63;
        Bf[c * LDF + r] = A[e];
    }
    if (tid == 0) nsig = 0;
    __syncthreads();

    // ---- In-place Cholesky: Bf (full symmetric A) -> L, column by column.
    // Full-column rank-1 updates m_j -= m_k * (m_k[j]/diag) naturally leave
    // rows < k at ~0 (M = sum_{i>=k} l_i l_i^T and l_i[r]=0 for r<i), so no
    // triangle masking is needed. Group g updates cols k+1+g and k+33+g. ----
    for (int k = 0; k < MDIM; k++) {
        // read phase
        float diag = Bf[k * LDF + k];
        float4 ck  = Bs4[k * LD4 + hl];
        int j  = k + 1 + pairid;
        int j2 = j + 32;
        float mk0 = (j  < MDIM) ? Bf[k * LDF + j ] : 0.0f;
        float mk1 = (j2 < MDIM) ? Bf[k * LDF + j2] : 0.0f;
        float inv = __fdividef(1.0f, diag);
        float rs  = rsqrtf(diag);
        __syncthreads();
        // write phase (each column touched by exactly one group)
        if (j < MDIM) {
            float m = mk0 * inv;
            float4 cj = Bs4[j * LD4 + hl];
            cj.x = fmaf(-m, ck.x, cj.x);
            cj.y = fmaf(-m, ck.y, cj.y);
            cj.z = fmaf(-m, ck.z, cj.z);
            cj.w = fmaf(-m, ck.w, cj.w);
            Bs4[j * LD4 + hl] = cj;
        }
        if (j2 < MDIM) {
            float m = mk1 * inv;
            float4 cj = Bs4[j2 * LD4 + hl];
            cj.x = fmaf(-m, ck.x, cj.x);
            cj.y = fmaf(-m, ck.y, cj.y);
            cj.z = fmaf(-m, ck.z, cj.z);
            cj.w = fmaf(-m, ck.w, cj.w);
            Bs4[j2 * LD4 + hl] = cj;
        }
        if (pairid == 31) {             // scale finished column k by 1/sqrt(diag)
            Bs4[k * LD4 + hl] = make_float4(ck.x * rs, ck.y * rs,
                                            ck.z * rs, ck.w * rs);
        }
        __syncthreads();
    }

    // ---- One-sided Jacobi sweeps on L (adaptive) ----
    for (int sw = 0; sw < MAXSWEEP; sw++) {
        // Exact column norms at sweep start: group g -> cols g, g+32.
        #pragma unroll
        for (int h = 0; h < 2; h++) {
            int k = pairid + 32 * h;
            float4 X = Bs4[k * LD4 + hl];
            u64 xa = pk2(X.x, X.y), xb = pk2(X.z, X.w);
            float2 f = upk(fma2(xb, xb, mul2(xa, xa)));
            float n2 = half_sum(f.x + f.y);
            if (hl == 0) cn[k] = n2;
        }
        __syncthreads();

        // Round-robin tournament: p,q step +1 mod 63 (pair 0: p=63 fixed).
        int p = (pairid == 0) ? 63 : pairid;
        int q = (pairid == 0) ? 0  : 63 - pairid;

        for (int rr = 0; rr < 63; rr++) {
            float4 P = Bs4[p * LD4 + hl];
            float4 Q = Bs4[q * LD4 + hl];
            float app = cn[p], aqq = cn[q];

            u64 pxy = pk2(P.x, P.y), pzw = pk2(P.z, P.w);
            u64 qxy = pk2(Q.x, Q.y), qzw = pk2(Q.z, Q.w);

            float2 df = upk(fma2(pzw, qzw, mul2(pxy, qxy)));
            float apq = half_sum(df.x + df.y);

            float a2 = apq * apq, pr = app * aqq;
            bool rot = a2 > RTOL * pr;              // uniform per group
            if (__any_sync(0xffffffffu, rot)) {
                float th  = __fdividef(aqq - app, 2.0f * apq);
                float h2  = fmaf(th, th, 1.0f);
                float hyp = h2 * rsqrtf(h2);                 // sqrt(1+th^2)
                float t   = copysignf(__fdividef(1.0f, fabsf(th) + hyp), th);
                float c   = rsqrtf(fmaf(t, t, 1.0f));
                float s   = t * c;

                if (rot) {
                    u64 cc = pk2(c, c), ss = pk2(s, s), ns = pk2(-s, -s);
                    float2 a0 = upk(fma2(cc, pxy, mul2(ns, qxy)));
                    float2 a1 = upk(fma2(cc, pzw, mul2(ns, qzw)));
                    float2 b0 = upk(fma2(cc, qxy, mul2(ss, pxy)));
                    float2 b1 = upk(fma2(cc, qzw, mul2(ss, pzw)));
                    Bs4[p * LD4 + hl] = make_float4(a0.x, a0.y, a1.x, a1.y);
                    Bs4[q * LD4 + hl] = make_float4(b0.x, b0.y, b1.x, b1.y);
                    if (hl == 0) {
                        cn[p] = app - t * apq;
                        cn[q] = aqq + t * apq;
                        if (a2 > QTOL * pr) nsig = 1;
                    }
                }
            }
            __syncthreads();

            if (pairid) { p++; if (p == 63) p = 0; }
            q++; if (q == 63) q = 0;
        }

        int sdone = nsig;
        __syncthreads();
        if (tid == 0) nsig = 0;
        __syncthreads();
        if (sdone == 0) break;
    }

    // ---- dv_k = log(lambda_k)/lambda_k, lambda_k = ||w_k||^2 = n2 ----
    #pragma unroll
    for (int h = 0; h < 2; h++) {
        int k = pairid + 32 * h;
        float4 X = Bs4[k * LD4 + hl];
        u64 xa = pk2(X.x, X.y), xb = pk2(X.z, X.w);
        float2 f = upk(fma2(xb, xb, mul2(xa, xa)));
        float n2 = half_sum(f.x + f.y);
        if (hl == 0) dv[k] = logf(n2) / n2;
    }
    __syncthreads();

    // ---- out[i][j] = sum_k dv[k]*W[i,k]*W[j,k], i<=j.
    //      Warp w owns rows {w, 63-w, 16+w, 47-w}; lanes cover j-pairs with
    //      float2 loads + packed FMA. ----
    #pragma unroll
    for (int rsel = 0; rsel < 4; rsel++) {
        int i = (rsel == 0) ? warp
              : (rsel == 1) ? 63 - warp
              : (rsel == 2) ? 16 + warp
                            : 47 - warp;
        int basei = i * (129 - i) / 2;
        int je = i & ~1;                 // even start so float2 loads align
        int j0 = je + 2 * lane;
        if (j0 < MDIM) {
            u64 acc = 0;                 // packed (0.0f, 0.0f)
            #pragma unroll
            for (int k = 0; k < MDIM; k++) {
                float ci = dv[k] * Bf[k * LDF + i];
                const float2 bj = *(const float2*)(Bf + k * LDF + j0);
                acc = fma2(pk2(ci, ci), pk2(bj.x, bj.y), acc);
            }
            float2 r = upk(acc);
            if (j0 >= i) O[basei + (j0 - i)] = r.x;
            O[basei + (j0 + 1 - i)] = r.y;
        }
    }
}

extern "C" void kernel_launch(void* const* d_in, const int* in_sizes, int n_in,
                              void* d_out, int out_size)
{
    const float* A = (const float*)d_in[0];
    float* out = (float*)d_out;
    int batch = in_sizes[0] / (MDIM * MDIM);   // 8192
    spd_log_kernel<<<batch, 512>>>(A, out);
}

// round 16
// speedup vs baseline: 1.7479x; 1.4094x over previous
#include <cuda_runtime.h>

// SPD log-map: for each 64x64 SPD matrix A, compute logm(A) = U diag(log w) U^T
// and emit the row-major upper triangle (2080 floats).
//
// One-sided Jacobi on B := A; at convergence columns are orthogonal with
// norms^2 = lambda^2, and logm(A) = B diag(0.5*log(n2)/n2) B^T.
//
// R16: BLOCK-2 round-robin. Columns grouped in 32 blocks of 2; tournament on
// 32 nodes = 31 block-rounds/sweep. A 16-lane group loads its meeting's 4
// columns ONCE (4 LDS.128), rotates 4 cross pairs (plus 2 intra pairs in
// round 0) entirely in registers, stores once, one barrier. Exactly C(64,2)
// pairs per sweep. Halves smem traffic AND barrier count vs R12 while keeping
// the proven tournament ordering and per-pair math (packed f32x2, 4-shfl
// group reduction, MUFU div/sqrt, cached norms, adaptive sweep stop).

#define MDIM 64
#define LDF  68          // floats per column slot (column base 272B, 16B-aligned)
#define LD4  17          // float4 stride
#define MAXSWEEP 24
#define NTRI 2080
#define RTOL 1e-13f      // rotate above ~3e-7 relative orthogonality
#define QTOL 1e-8f       // sweep "significant" above ~1e-4 relative

typedef unsigned long long u64;

__device__ __forceinline__ u64 pk2(float x, float y) {
    u64 r; asm("mov.b64 %0, {%1, %2};" : "=l"(r) : "f"(x), "f"(y)); return r;
}
__device__ __forceinline__ float2 upk(u64 v) {
    float lo, hi; asm("mov.b64 {%0, %1}, %2;" : "=f"(lo), "=f"(hi) : "l"(v));
    return make_float2(lo, hi);
}
__device__ __forceinline__ u64 mul2(u64 a, u64 b) {
    u64 r; asm("mul.rn.f32x2 %0, %1, %2;" : "=l"(r) : "l"(a), "l"(b)); return r;
}
__device__ __forceinline__ u64 fma2(u64 a, u64 b, u64 c) {
    u64 r; asm("fma.rn.f32x2 %0, %1, %2, %3;" : "=l"(r) : "l"(a), "l"(b), "l"(c));
    return r;
}

__device__ __forceinline__ float half_sum(float v) {
    #pragma unroll
    for (int o = 8; o; o >>= 1)
        v += __shfl_xor_sync(0xffffffffu, v, o);
    return v;                 // sum within each 16-lane group
}

// One Jacobi rotation on register-resident columns u, v (u64-packed float4
// slices) with cached squared norms nu, nv. Group-uniform decisions.
__device__ __forceinline__ void jrot(u64& ux, u64& uz, u64& vx, u64& vz,
                                     float& nu, float& nv, int& sig, int& moved)
{
    float2 df = upk(fma2(uz, vz, mul2(ux, vx)));
    float apq = half_sum(df.x + df.y);
    float a2 = apq * apq, pr = nu * nv;
    bool rot = a2 > RTOL * pr;
    if (__any_sync(0xffffffffu, rot)) {
        float th  = __fdividef(nv - nu, 2.0f * apq);
        float h2  = fmaf(th, th, 1.0f);
        float hyp = h2 * rsqrtf(h2);                 // sqrt(1+th^2)
        float t   = copysignf(__fdividef(1.0f, fabsf(th) + hyp), th);
        float c   = rsqrtf(fmaf(t, t, 1.0f));
        float s   = t * c;
        if (rot) {
            u64 cc = pk2(c, c), ss = pk2(s, s), ns = pk2(-s, -s);
            u64 nux = fma2(cc, ux, mul2(ns, vx));
            u64 nuz = fma2(cc, uz, mul2(ns, vz));
            vx = fma2(cc, vx, mul2(ss, ux));
            vz = fma2(cc, vz, mul2(ss, uz));
            ux = nux; uz = nuz;
            nu -= t * apq;
            nv += t * apq;
            moved = 1;
            if (a2 > QTOL * pr) sig = 1;
        }
    }
}

__global__ __launch_bounds__(256, 6)
void spd_log_kernel(const float* __restrict__ in, float* __restrict__ out)
{
    __shared__ float4 Bs4[MDIM * LD4];  // column c: float4 g = rows 4g..4g+3
    __shared__ float  cn[MDIM];
    __shared__ float  dv[MDIM];
    __shared__ int    nsig;

    const int tid    = threadIdx.x;
    const int pairid = tid >> 4;        // 0..15: 16-lane group id = meeting id
    const int hl     = tid & 15;        // lane within group
    const int warp   = tid >> 5;        // 0..7
    const int lane   = tid & 31;

    float* Bf = (float*)Bs4;            // B[r, c] == Bf[c*LDF + r]

    const float* A = in  + (size_t)blockIdx.x * (MDIM * MDIM);
    float*       O = out + (size_t)blockIdx.x * NTRI;

    // Load (A symmetric): Bf[c*LDF + r] = A[c*64 + r]; contiguous both sides.
    for (int e = tid; e < MDIM * MDIM; e += 256) {
        int c = e >> 6, r = e & 63;
        Bf[c * LDF + r] = A[e];
    }
    if (tid == 0) nsig = 0;
    __syncthreads();

    // ---- One-sided Jacobi sweeps (adaptive) ----
    for (int sw = 0; sw < MAXSWEEP; sw++) {
        // Exact column norms at sweep start: group g -> cols g, g+16, g+32, g+48.
        #pragma unroll
        for (int h = 0; h < 4; h++) {
            int k = pairid + 16 * h;
            float4 X = Bs4[k * LD4 + hl];
            u64 xa = pk2(X.x, X.y), xb = pk2(X.z, X.w);
            float2 f = upk(fma2(xb, xb, mul2(xa, xa)));
            float n2 = half_sum(f.x + f.y);
            if (hl == 0) cn[k] = n2;
        }
        __syncthreads();

        // Block tournament on 32 nodes (blocks of 2 columns), 31 rounds.
        int pn = (pairid == 0) ? 31 : pairid;
        int qn = (pairid == 0) ? 0  : 31 - pairid;

        for (int rr = 0; rr < 31; rr++) {
            const int ca = 2 * pn, cb = ca + 1;
            const int cc = 2 * qn, cd = cc + 1;

            float4 XA = Bs4[ca * LD4 + hl];
            float4 XB = Bs4[cb * LD4 + hl];
            float4 XC = Bs4[cc * LD4 + hl];
            float4 XD = Bs4[cd * LD4 + hl];
            u64 ax = pk2(XA.x, XA.y), az = pk2(XA.z, XA.w);
            u64 bx = pk2(XB.x, XB.y), bz = pk2(XB.z, XB.w);
            u64 cx = pk2(XC.x, XC.y), cz = pk2(XC.z, XC.w);
            u64 dx = pk2(XD.x, XD.y), dz = pk2(XD.z, XD.w);
            float na = cn[ca], nb = cn[cb], nc = cn[cc], nd = cn[cd];

            int sig = 0, moved = 0;

            if (rr == 0) {                       // intra-block pairs, once/sweep
                jrot(ax, az, bx, bz, na, nb, sig, moved);
                jrot(cx, cz, dx, dz, nc, nd, sig, moved);
            }
            // cross pairs (all 4 combinations of the two blocks)
            jrot(ax, az, cx, cz, na, nc, sig, moved);
            jrot(bx, bz, dx, dz, nb, nd, sig, moved);
            jrot(ax, az, dx, dz, na, nd, sig, moved);
            jrot(bx, bz, cx, cz, nb, nc, sig, moved);

            if (moved) {
                float2 f0, f1;
                f0 = upk(ax); f1 = upk(az);
                Bs4[ca * LD4 + hl] = make_float4(f0.x, f0.y, f1.x, f1.y);
                f0 = upk(bx); f1 = upk(bz);
                Bs4[cb * LD4 + hl] = make_float4(f0.x, f0.y, f1.x, f1.y);
                f0 = upk(cx); f1 = upk(cz);
                Bs4[cc * LD4 + hl] = make_float4(f0.x, f0.y, f1.x, f1.y);
                f0 = upk(dx); f1 = upk(dz);
                Bs4[cd * LD4 + hl] = make_float4(f0.x, f0.y, f1.x, f1.y);
                if (hl == 0) {
                    cn[ca] = na; cn[cb] = nb; cn[cc] = nc; cn[cd] = nd;
                    if (sig) nsig = 1;
                }
            }
            __syncthreads();

            if (pairid) { pn++; if (pn == 31) pn = 0; }
            qn++; if (qn == 31) qn = 0;
        }

        int sdone = nsig;
        __syncthreads();
        if (tid == 0) nsig = 0;
        __syncthreads();
        if (sdone == 0) break;
    }

    // ---- dv_k = log(l_k)/l_k^2 = 0.5*log(n2)/n2, n2 = l^2 ----
    #pragma unroll
    for (int h = 0; h < 4; h++) {
        int k = pairid + 16 * h;
        float4 X = Bs4[k * LD4 + hl];
        u64 xa = pk2(X.x, X.y), xb = pk2(X.z, X.w);
        float2 f = upk(fma2(xb, xb, mul2(xa, xa)));
        float n2 = half_sum(f.x + f.y);
        if (hl == 0) dv[k] = 0.5f * logf(n2) / n2;
    }
    __syncthreads();

    // ---- out[i][j] = sum_k dv[k]*B[i,k]*B[j,k], i<=j.
    //      8 warps; warp w owns rows {8m+w, 63-(8m+w)}, m=0..3 (balanced).
    //      Lanes cover j-pairs with float2 loads + packed FMA. ----
    #pragma unroll
    for (int m = 0; m < 4; m++) {
        #pragma unroll
        for (int hs = 0; hs < 2; hs++) {
            int i = hs ? 63 - (8 * m + warp) : 8 * m + warp;
            int basei = i * (129 - i) / 2;
            int je = i & ~1;             // even start so float2 loads align
            int j0 = je + 2 * lane;
            if (j0 < MDIM) {
                u64 acc = 0;             // packed (0.0f, 0.0f)
                #pragma unroll
                for (int k = 0; k < MDIM; k++) {
                    float ci = dv[k] * Bf[k * LDF + i];
                    const float2 bj = *(const float2*)(Bf + k * LDF + j0);
                    acc = fma2(pk2(ci, ci), pk2(bj.x, bj.y), acc);
                }
                float2 r = upk(acc);
                if (j0 >= i) O[basei + (j0 - i)] = r.x;
                O[basei + (j0 + 1 - i)] = r.y;
            }
        }
    }
}

extern "C" void kernel_launch(void* const* d_in, const int* in_sizes, int n_in,
                              void* d_out, int out_size)
{
    const float* A = (const float*)d_in[0];
    float* out = (float*)d_out;
    int batch = in_sizes[0] / (MDIM * MDIM);   // 8192
    spd_log_kernel<<<batch, 256>>>(A, out);
}